// round 13
// baseline (speedup 1.0000x reference)
#include <cuda_runtime.h>
#include <cstdint>

// Problem constants
#define BB   2
#define SS   2048
#define DD   1024
#define HH   16
#define HD   64
#define MTOT (BB*SS)   // 4096
#define GK   1024

// Scratch (allocation-free: __device__ globals)
__device__ float g_Q[MTOT*DD];
__device__ float g_K[MTOT*DD];
__device__ float g_V[MTOT*DD];
__device__ float g_C[MTOT*DD];
__device__ float g_X[MTOT*DD];     // tf32-truncated x
__device__ float g_Wq[DD*DD];      // tf32-truncated weights
__device__ float g_Wk[DD*DD];
__device__ float g_Wv[DD*DD];
__device__ float g_Wo[DD*DD];

// ---------------------------------------------------------------------------
// helpers
// ---------------------------------------------------------------------------
__device__ __forceinline__ uint32_t f2tf32(float f) {
    uint32_t r;
    asm("cvt.rna.tf32.f32 %0, %1;" : "=r"(r) : "f"(f));
    return r;
}
__device__ __forceinline__ void mma_tf32(float* c, const uint32_t* a, const uint32_t* b) {
    asm volatile(
        "mma.sync.aligned.m16n8k8.row.col.f32.tf32.tf32.f32 "
        "{%0,%1,%2,%3}, {%4,%5,%6,%7}, {%8,%9}, {%0,%1,%2,%3};"
        : "+f"(c[0]), "+f"(c[1]), "+f"(c[2]), "+f"(c[3])
        : "r"(a[0]), "r"(a[1]), "r"(a[2]), "r"(a[3]), "r"(b[0]), "r"(b[1]));
}
__device__ __forceinline__ uint32_t fbits(float f) { return __float_as_uint(f); }

__device__ __forceinline__ uint32_t smem_u32(const void* p) {
    uint32_t a;
    asm("{ .reg .u64 t; cvta.to.shared.u64 t, %1; cvt.u32.u64 %0, t; }"
        : "=r"(a) : "l"(p));
    return a;
}
#define LDSM_X4(r0, r1, r2, r3, addr) \
    asm volatile("ldmatrix.sync.aligned.m8n8.x4.shared.b16 {%0,%1,%2,%3}, [%4];" \
                 : "=r"(r0), "=r"(r1), "=r"(r2), "=r"(r3) : "r"(addr))
#define CP16(dst, src) \
    asm volatile("cp.async.ca.shared.global [%0], [%1], 16;" \
                 :: "r"(dst), "l"(src) : "memory")
#define CP_COMMIT() asm volatile("cp.async.commit_group;" ::: "memory")
#define CP_WAIT2()  asm volatile("cp.async.wait_group 2;" ::: "memory")
#define CP_WAIT1()  asm volatile("cp.async.wait_group 1;" ::: "memory")
#define CP_WAIT0()  asm volatile("cp.async.wait_group 0;" ::: "memory")

// ===========================================================================
// prep: tf32-truncate x and the 4 weight matrices (one pass, float4).
// ===========================================================================
__global__ __launch_bounds__(256)
void prep_cvt(const float* __restrict__ x,
              const float* __restrict__ wq, const float* __restrict__ wk,
              const float* __restrict__ wv, const float* __restrict__ wo,
              float* __restrict__ gx,
              float* __restrict__ gwq, float* __restrict__ gwk,
              float* __restrict__ gwv, float* __restrict__ gwo)
{
    const int slice = blockIdx.x >> 10;
    const int bx    = blockIdx.x & 1023;
    const size_t i4 = (size_t)bx * 256 + threadIdx.x;

    const float* src;
    float* dst;
    if (slice < 4) { src = x + (size_t)slice * 1048576; dst = gx + (size_t)slice * 1048576; }
    else if (slice == 4) { src = wq; dst = gwq; }
    else if (slice == 5) { src = wk; dst = gwk; }
    else if (slice == 6) { src = wv; dst = gwv; }
    else                 { src = wo; dst = gwo; }

    float4 v = reinterpret_cast<const float4*>(src)[i4];
    float4 o;
    o.x = __uint_as_float(f2tf32(v.x));
    o.y = __uint_as_float(f2tf32(v.y));
    o.z = __uint_as_float(f2tf32(v.z));
    o.w = __uint_as_float(f2tf32(v.w));
    reinterpret_cast<float4*>(dst)[i4] = o;
}

// ===========================================================================
// GEMM: C[M,N] = A[M,K] @ W[N,K]^T, K=1024, operands pre-truncated to tf32.
// CTA 128x128, BK=16, 4-stage cp.async ring, ldmatrix frags, 2 CTAs/SM.
// ===========================================================================
#define NS     4
#define GST    20
#define GTILE  (128*GST)
#define GTILEB (GTILE*4)          // 10240 B
#define GSTAGEB (2*GTILEB)        // 20480 B
#define GEMM_SMEM (NS*GSTAGEB)    // 81920 B

__device__ __forceinline__
void gemm_body(const float* __restrict__ A, const float* __restrict__ W,
               float* __restrict__ C, int N, char* smc)
{
    const uint32_t sbase = smem_u32(smc);
    const int tid  = threadIdx.x;
    const int wid  = tid >> 5;
    const int lane = tid & 31;
    const int gp   = lane >> 2;
    const int tg   = lane & 3;
    const int wr   = wid & 1;
    const int wc   = wid >> 1;
    const int m0   = blockIdx.y << 7;
    const int n0   = blockIdx.x << 7;

    const float* Ap = A + (size_t)m0 * GK;
    const float* Wp = W + (size_t)n0 * GK;

    int srow[2], sc4[2];
#pragma unroll
    for (int u = 0; u < 2; u++) {
        int g = tid + (u << 8);
        srow[u] = g >> 2;
        sc4[u]  = (g & 3) << 2;
    }

    const int aRow = wr * 64 + (lane & 15);
    const int aSel = (lane >> 4) << 2;
    const int bRow = wc * 32 + ((lane >> 4) << 3) + (lane & 7);
    const int bSel = ((lane >> 3) & 1) << 2;

    float acc[16][4];
#pragma unroll
    for (int i = 0; i < 16; i++)
#pragma unroll
        for (int j = 0; j < 4; j++) acc[i][j] = 0.f;

#pragma unroll
    for (int s = 0; s < NS - 1; s++) {
        const int kt = s << 4;
        const uint32_t stg = sbase + s * GSTAGEB;
#pragma unroll
        for (int u = 0; u < 2; u++) {
            CP16(stg + (uint32_t)((srow[u] * GST + sc4[u]) * 4),
                 Ap + (size_t)srow[u] * GK + kt + sc4[u]);
            CP16(stg + GTILEB + (uint32_t)((srow[u] * GST + sc4[u]) * 4),
                 Wp + (size_t)srow[u] * GK + kt + sc4[u]);
        }
        CP_COMMIT();
    }

    const int NCH = GK / 16;   // 64
    for (int i = 0; i < NCH; i++) {
        CP_WAIT2();
        __syncthreads();

        if (i + NS - 1 < NCH) {
            const int kt = (i + NS - 1) << 4;
            const uint32_t stg = sbase + ((i + NS - 1) & (NS - 1)) * GSTAGEB;
#pragma unroll
            for (int u = 0; u < 2; u++) {
                CP16(stg + (uint32_t)((srow[u] * GST + sc4[u]) * 4),
                     Ap + (size_t)srow[u] * GK + kt + sc4[u]);
                CP16(stg + GTILEB + (uint32_t)((srow[u] * GST + sc4[u]) * 4),
                     Wp + (size_t)srow[u] * GK + kt + sc4[u]);
            }
        }
        CP_COMMIT();

        const uint32_t sA = sbase + (i & (NS - 1)) * GSTAGEB;
        const uint32_t sB = sA + GTILEB;
#pragma unroll
        for (int kk = 0; kk < 2; kk++) {
            uint32_t af[4][4], bf[4][2];
#pragma unroll
            for (int tm = 0; tm < 4; tm++) {
                uint32_t addr = sA + (uint32_t)(((aRow + tm * 16) * GST + kk * 8 + aSel) * 4);
                LDSM_X4(af[tm][0], af[tm][1], af[tm][2], af[tm][3], addr);
            }
#pragma unroll
            for (int p = 0; p < 2; p++) {
                uint32_t addr = sB + (uint32_t)(((bRow + p * 16) * GST + kk * 8 + bSel) * 4);
                LDSM_X4(bf[2*p][0], bf[2*p][1], bf[2*p+1][0], bf[2*p+1][1], addr);
            }
#pragma unroll
            for (int tm = 0; tm < 4; tm++)
#pragma unroll
                for (int tn = 0; tn < 4; tn++)
                    mma_tf32(acc[tm * 4 + tn], af[tm], bf[tn]);
        }
    }

#pragma unroll
    for (int tm = 0; tm < 4; tm++) {
        const int r = m0 + wr * 64 + tm * 16 + gp;
#pragma unroll
        for (int tn = 0; tn < 4; tn++) {
            const int c = n0 + wc * 32 + tn * 8 + 2 * tg;
            float* p0 = C + (size_t)r * N + c;
            float* p1 = C + (size_t)(r + 8) * N + c;
            *reinterpret_cast<float2*>(p0) = make_float2(acc[tm*4+tn][0], acc[tm*4+tn][1]);
            *reinterpret_cast<float2*>(p1) = make_float2(acc[tm*4+tn][2], acc[tm*4+tn][3]);
        }
    }
}

__global__ __launch_bounds__(256, 2)
void gemm_mma(const float* __restrict__ A, const float* __restrict__ W,
              float* __restrict__ C, int N)
{
    extern __shared__ char smc[];
    gemm_body(A, W, C, N, smc);
}

__global__ __launch_bounds__(256, 2)
void gemm_qkv(const float* __restrict__ x,
              const float* __restrict__ Wq, const float* __restrict__ Wk,
              const float* __restrict__ Wv,
              float* __restrict__ Qo, float* __restrict__ Ko, float* __restrict__ Vo)
{
    extern __shared__ char smc[];
    const int z = blockIdx.z;
    const float* W = (z == 0) ? Wq : (z == 1) ? Wk : Wv;
    float* C = (z == 0) ? Qo : (z == 1) ? Ko : Vo;
    gemm_body(x, W, C, DD, smc);
}

// ===========================================================================
// Flash attention (mma.sync tf32): Q frags in regs, cp.async K/V double-buffer,
// cp.async mask prefetch, P via per-warp smem tile + ldmatrix (no shuffles).
// ===========================================================================
#define KST 68
#define VST 72
#define MST 68
#define PST 68
#define KB0 0
#define VB0 (64*KST)
#define KB1 (VB0 + 64*VST)
#define VB1 (KB1 + 64*KST)
#define MB  (VB1 + 64*VST)               // mask: 128 x MST
#define PB  (MB + 128*MST)               // P: 8 warps x 16 x PST
#define ATTN_SMEM ((PB + 8*16*PST)*4)    // 141312 B

__global__ __launch_bounds__(256, 1)
void attn_mma(const float* __restrict__ Q, const float* __restrict__ Kg,
              const float* __restrict__ V, const float* __restrict__ mask,
              float* __restrict__ ctx)
{
    extern __shared__ float sm[];
    const uint32_t sbase = smem_u32(sm);

    const int tid  = threadIdx.x;
    const int wid  = tid >> 5;
    const int lane = tid & 31;
    const int gp   = lane >> 2;
    const int tg   = lane & 3;

    const int qt = blockIdx.x;
    const int h  = blockIdx.y;
    const int b  = blockIdx.z;

    const int q0g  = b * SS + qt * 128;
    const int col0 = h * HD;
    const float scale = 0.03125f;

    int grow[4], gc4[4];
#pragma unroll
    for (int u = 0; u < 4; u++) {
        int g = tid + (u << 8);
        grow[u] = g >> 4;
        gc4[u]  = (g & 15) << 2;
    }

    // ldmatrix address components
    const int kRowOff = ((lane >> 4) << 3) + (lane & 7);
    const int kSel    = ((lane >> 3) & 1) << 2;
    const int pRow    = lane & 15;            // A-frag rows
    const int pSel    = (lane >> 4) << 2;

    // ---- issue K/V tile 0
    {
        const int k0 = b * SS;
#pragma unroll
        for (int u = 0; u < 4; u++) {
            const float* ks = Kg + (size_t)(k0 + grow[u]) * DD + col0 + gc4[u];
            const float* vs = V  + (size_t)(k0 + grow[u]) * DD + col0 + gc4[u];
            CP16(sbase + (KB0 + grow[u] * KST + gc4[u]) * 4, ks);
            CP16(sbase + (VB0 + grow[u] * VST + gc4[u]) * 4, vs);
        }
        CP_COMMIT();
    }

    // ---- Q fragments in registers
    const int qm0 = wid * 16;
    uint32_t qf[8][4];
    {
        const float* q0p = Q + (size_t)(q0g + qm0 + gp) * DD + col0;
        const float* q1p = q0p + 8 * DD;
#pragma unroll
        for (int kk = 0; kk < 8; kk++) {
            const int c = kk * 8 + tg;
            qf[kk][0] = f2tf32(q0p[c]);
            qf[kk][1] = f2tf32(q1p[c]);
            qf[kk][2] = f2tf32(q0p[c + 4]);
            qf[kk][3] = f2tf32(q1p[c + 4]);
        }
    }

    float mprev0 = -1e30f, mprev1 = -1e30f;
    float lsum0 = 0.f, lsum1 = 0.f;
    float O[8][4];
#pragma unroll
    for (int i = 0; i < 8; i++)
#pragma unroll
        for (int j = 0; j < 4; j++) O[i][j] = 0.f;

    const float* Ms0 = sm + MB + (qm0 + gp) * MST;
    const float* Ms1 = Ms0 + 8 * MST;
    const float* mtile0 = mask + (size_t)(qt * 128) * SS;

    // per-warp P tile
    float* Pw = sm + PB + wid * 16 * PST;
    float* Pw0 = Pw + gp * PST + 2 * tg;
    float* Pw1 = Pw0 + 8 * PST;
    const uint32_t sP = sbase + (uint32_t)((PB + wid * 16 * PST) * 4);
    const uint32_t pAddrBase = sP + (uint32_t)((pRow * PST + pSel) * 4);

    const int NT = SS / 64;
    for (int t = 0; t < NT; t++) {
        const int bsel = t & 1;

        // issue mask tile t (committed BEFORE KV_{t+1})
        {
            const float* mb = mtile0 + t * 64;
#pragma unroll
            for (int u = 0; u < 8; u++) {
                int g = tid + (u << 8);
                int r = g >> 4;
                int c4 = (g & 15) << 2;
                CP16(sbase + (uint32_t)((MB + r * MST + c4) * 4),
                     mb + (size_t)r * SS + c4);
            }
            CP_COMMIT();
        }
        // issue K/V for t+1
        if (t + 1 < NT) {
            const int k1 = b * SS + (t + 1) * 64;
            const int kb = bsel ? KB0 : KB1;
            const int vb = bsel ? VB0 : VB1;
#pragma unroll
            for (int u = 0; u < 4; u++) {
                const float* ks = Kg + (size_t)(k1 + grow[u]) * DD + col0 + gc4[u];
                const float* vs = V  + (size_t)(k1 + grow[u]) * DD + col0 + gc4[u];
                CP16(sbase + (kb + grow[u] * KST + gc4[u]) * 4, ks);
                CP16(sbase + (vb + grow[u] * VST + gc4[u]) * 4, vs);
            }
        }
        CP_COMMIT();

        CP_WAIT2();    // K/V tile t resident
        __syncthreads();

        const uint32_t sK = sbase + (bsel ? KB1 : KB0) * 4;
        const float* Vs = sm + (bsel ? VB1 : VB0);

        // --- S = Q K^T
        float sacc[8][4];
#pragma unroll
        for (int nt = 0; nt < 8; nt++)
#pragma unroll
            for (int j = 0; j < 4; j++) sacc[nt][j] = 0.f;

#pragma unroll
        for (int kk = 0; kk < 8; kk++) {
#pragma unroll
            for (int p = 0; p < 4; p++) {
                uint32_t b0[2], b1[2];
                uint32_t addr = sK + (uint32_t)(((p * 16 + kRowOff) * KST + kk * 8 + kSel) * 4);
                LDSM_X4(b0[0], b0[1], b1[0], b1[1], addr);
                mma_tf32(sacc[2*p],     qf[kk], b0);
                mma_tf32(sacc[2*p + 1], qf[kk], b1);
            }
        }

        CP_WAIT1();    // mask tile t resident
        __syncthreads();

        // --- mask (smem) + scale, online softmax
        float mx0 = -1e30f, mx1 = -1e30f;
#pragma unroll
        for (int nt = 0; nt < 8; nt++) {
            const int kc = nt * 8 + 2 * tg;
            float2 mk0 = *reinterpret_cast<const float2*>(Ms0 + kc);
            float2 mk1 = *reinterpret_cast<const float2*>(Ms1 + kc);
            sacc[nt][0] = (sacc[nt][0] + mk0.x) * scale;
            sacc[nt][1] = (sacc[nt][1] + mk0.y) * scale;
            sacc[nt][2] = (sacc[nt][2] + mk1.x) * scale;
            sacc[nt][3] = (sacc[nt][3] + mk1.y) * scale;
            mx0 = fmaxf(mx0, fmaxf(sacc[nt][0], sacc[nt][1]));
            mx1 = fmaxf(mx1, fmaxf(sacc[nt][2], sacc[nt][3]));
        }
#pragma unroll
        for (int off = 1; off <= 2; off <<= 1) {
            mx0 = fmaxf(mx0, __shfl_xor_sync(0xffffffffu, mx0, off));
            mx1 = fmaxf(mx1, __shfl_xor_sync(0xffffffffu, mx1, off));
        }
        const float mn0 = fmaxf(mprev0, mx0);
        const float mn1 = fmaxf(mprev1, mx1);
        const float al0 = __expf(mprev0 - mn0);
        const float al1 = __expf(mprev1 - mn1);
        mprev0 = mn0; mprev1 = mn1;

        float rs0 = 0.f, rs1 = 0.f;
#pragma unroll
        for (int nt = 0; nt < 8; nt++) {
            sacc[nt][0] = __expf(sacc[nt][0] - mn0);
            sacc[nt][1] = __expf(sacc[nt][1] - mn0);
            sacc[nt][2] = __expf(sacc[nt][2] - mn1);
            sacc[nt][3] = __expf(sacc[nt][3] - mn1);
            rs0 += sacc[nt][0] + sacc[nt][1];
            rs1 += sacc[nt][2] + sacc[nt][3];
            // stage P into per-warp smem tile (accumulator layout)
            *reinterpret_cast<float2*>(Pw0 + nt * 8) = make_float2(sacc[nt][0], sacc[nt][1]);
            *reinterpret_cast<float2*>(Pw1 + nt * 8) = make_float2(sacc[nt][2], sacc[nt][3]);
        }
#pragma unroll
        for (int off = 1; off <= 2; off <<= 1) {
            rs0 += __shfl_xor_sync(0xffffffffu, rs0, off);
            rs1 += __shfl_xor_sync(0xffffffffu, rs1, off);
        }
        lsum0 = lsum0 * al0 + rs0;
        lsum1 = lsum1 * al1 + rs1;

#pragma unroll
        for (int nt = 0; nt < 8; nt++) {
            O[nt][0] *= al0; O[nt][1] *= al0;
            O[nt][2] *= al1; O[nt][3] *= al1;
        }
        __syncwarp();

        // --- O += P V ; P A-fragments via ldmatrix from per-warp tile
#pragma unroll
        for (int kk = 0; kk < 8; kk++) {
            uint32_t af[4];
            LDSM_X4(af[0], af[1], af[2], af[3],
                    pAddrBase + (uint32_t)(kk * 8 * 4));
#pragma unroll
            for (int nt = 0; nt < 8; nt++) {
                uint32_t bf[2];
                const float* pv = Vs + (kk * 8 + tg) * VST + nt * 8 + gp;
                bf[0] = fbits(pv[0]);
                bf[1] = fbits(pv[4 * VST]);
                mma_tf32(O[nt], af, bf);
            }
        }
        __syncthreads();   // protect KV_t + mask before next-iter issues
    }

    // --- normalize + store context, pre-truncated for the Wo GEMM
    const float inv0 = 1.0f / lsum0;
    const float inv1 = 1.0f / lsum1;
    const int r0 = q0g + qm0 + gp;
#pragma unroll
    for (int nt = 0; nt < 8; nt++) {
        const int c = col0 + nt * 8 + 2 * tg;
        float2 v0 = make_float2(__uint_as_float(f2tf32(O[nt][0] * inv0)),
                                __uint_as_float(f2tf32(O[nt][1] * inv0)));
        float2 v1 = make_float2(__uint_as_float(f2tf32(O[nt][2] * inv1)),
                                __uint_as_float(f2tf32(O[nt][3] * inv1)));
        *reinterpret_cast<float2*>(ctx + (size_t)r0 * DD + c) = v0;
        *reinterpret_cast<float2*>(ctx + (size_t)(r0 + 8) * DD + c) = v1;
    }
}

// ---------------------------------------------------------------------------
extern "C" void kernel_launch(void* const* d_in, const int* in_sizes, int n_in,
                              void* d_out, int out_size)
{
    const float* x    = (const float*)d_in[0];
    const float* mask = (const float*)d_in[1];
    const float* Wq   = (const float*)d_in[2];
    const float* Wk   = (const float*)d_in[3];
    const float* Wv   = (const float*)d_in[4];
    const float* Wo   = (const float*)d_in[5];
    float* out = (float*)d_out;

    float *pQ, *pK, *pV, *pC, *pX, *pWq, *pWk, *pWv, *pWo;
    cudaGetSymbolAddress((void**)&pQ, g_Q);
    cudaGetSymbolAddress((void**)&pK, g_K);
    cudaGetSymbolAddress((void**)&pV, g_V);
    cudaGetSymbolAddress((void**)&pC, g_C);
    cudaGetSymbolAddress((void**)&pX, g_X);
    cudaGetSymbolAddress((void**)&pWq, g_Wq);
    cudaGetSymbolAddress((void**)&pWk, g_Wk);
    cudaGetSymbolAddress((void**)&pWv, g_Wv);
    cudaGetSymbolAddress((void**)&pWo, g_Wo);

    cudaFuncSetAttribute(gemm_qkv, cudaFuncAttributeMaxDynamicSharedMemorySize, GEMM_SMEM);
    cudaFuncSetAttribute(gemm_mma, cudaFuncAttributeMaxDynamicSharedMemorySize, GEMM_SMEM);
    cudaFuncSetAttribute(attn_mma, cudaFuncAttributeMaxDynamicSharedMemorySize, ATTN_SMEM);

    dim3 blk(256);

    prep_cvt<<<8192, blk>>>(x, Wq, Wk, Wv, Wo, pX, pWq, pWk, pWv, pWo);

    dim3 qkvgrid(DD / 128, MTOT / 128, 3);   // (8, 32, 3)
    gemm_qkv<<<qkvgrid, blk, GEMM_SMEM>>>(pX, pWq, pWk, pWv, pQ, pK, pV);

    dim3 agrid(SS / 128, HH, BB);            // (16, 16, 2)
    attn_mma<<<agrid, blk, ATTN_SMEM>>>(pQ, pK, pV, mask, pC);

    dim3 ggrid(DD / 128, MTOT / 128);        // (8, 32)
    gemm_mma<<<ggrid, blk, GEMM_SMEM>>>(pC, pWo, out, DD);
}